// round 9
// baseline (speedup 1.0000x reference)
#include <cuda_runtime.h>
#include <cuda_bf16.h>
#include <math.h>
#include <stdint.h>

#define T_TOKENS 4096
#define D_DIM    1024
#define H_DIM    2048
#define E_NUM    8

// ---------------- scratch (device globals; no runtime allocation) ----------
__device__ float g_probs[T_TOKENS * E_NUM];
__device__ float g_topval[T_TOKENS];
__device__ int   g_count[E_NUM];
__device__ int   g_toklist[E_NUM * T_TOKENS];
__device__ __nv_bfloat16 g_xb[T_TOKENS * D_DIM];          // x bf16 [T,D]
__device__ __nv_bfloat16 g_w1b[E_NUM * D_DIM * H_DIM];    // w1 bf16 [E][D][H]
__device__ __nv_bfloat16 g_w2b[E_NUM * H_DIM * D_DIM];    // w2 bf16 [E][H][D]
__device__ __nv_bfloat16 g_hb[T_TOKENS * H_DIM];          // hidden bf16 [T,H]
__device__ float g_y[T_TOKENS * D_DIM];                   // expert out * top_val

__device__ __forceinline__ float gelu_exact(float v) {
    return 0.5f * v * (1.0f + erff(v * 0.70710678118654752440f));
}

__device__ __forceinline__ uint32_t smem_u32(const void* p) {
    return (uint32_t)__cvta_generic_to_shared(p);
}

__device__ __forceinline__ void cp_async16(uint32_t dst, const void* src, int src_bytes) {
    asm volatile("cp.async.cg.shared.global [%0], [%1], 16, %2;\n"
                 :: "r"(dst), "l"(src), "r"(src_bytes));
}

__device__ __forceinline__ void ldsm_x4(uint32_t* r, uint32_t addr) {
    asm volatile("ldmatrix.sync.aligned.m8n8.x4.shared.b16 {%0,%1,%2,%3}, [%4];\n"
                 : "=r"(r[0]), "=r"(r[1]), "=r"(r[2]), "=r"(r[3]) : "r"(addr));
}

__device__ __forceinline__ void ldsm_x4_trans(uint32_t* r, uint32_t addr) {
    asm volatile("ldmatrix.sync.aligned.m8n8.x4.trans.shared.b16 {%0,%1,%2,%3}, [%4];\n"
                 : "=r"(r[0]), "=r"(r[1]), "=r"(r[2]), "=r"(r[3]) : "r"(addr));
}

__device__ __forceinline__ void mma_bf16(float* d, const uint32_t* a, uint32_t b0, uint32_t b1) {
    asm volatile("mma.sync.aligned.m16n8k16.row.col.f32.bf16.bf16.f32 "
                 "{%0,%1,%2,%3}, {%4,%5,%6,%7}, {%8,%9}, {%0,%1,%2,%3};\n"
                 : "+f"(d[0]), "+f"(d[1]), "+f"(d[2]), "+f"(d[3])
                 : "r"(a[0]), "r"(a[1]), "r"(a[2]), "r"(a[3]), "r"(b0), "r"(b1));
}

// ---------------- 0: zero counters ----------------
__global__ void zero_kernel() {
    if (threadIdx.x < E_NUM) g_count[threadIdx.x] = 0;
}

// ---------------- 0b: fp32 -> bf16 conversion ----------------
__global__ void convert_kernel(const float* __restrict__ src,
                               __nv_bfloat16* __restrict__ dst, int n) {
    int i = (blockIdx.x * blockDim.x + threadIdx.x) * 4;
    if (i < n) {
        float4 v = *(const float4*)(src + i);
        __nv_bfloat162* d = (__nv_bfloat162*)(dst + i);
        d[0] = __floats2bfloat162_rn(v.x, v.y);
        d[1] = __floats2bfloat162_rn(v.z, v.w);
    }
}

// ---------------- 1: gating (one warp per token) ----------------
__global__ void gate_kernel(const float* __restrict__ x,
                            const float* __restrict__ gw,
                            const float* __restrict__ gb) {
    const int warp = threadIdx.x >> 5;
    const int lane = threadIdx.x & 31;
    const int t = blockIdx.x * 8 + warp;
    const float4* xr4 = (const float4*)(x + (size_t)t * D_DIM);
    const float4* gw4 = (const float4*)gw;    // [D][8] -> 2 float4 per d

    float s[E_NUM];
    #pragma unroll
    for (int e = 0; e < E_NUM; e++) s[e] = 0.f;

    #pragma unroll
    for (int j = 0; j < 8; j++) {
        int i = lane + 32 * j;                // float4 index, d = 4i..4i+3
        float4 xv = xr4[i];
        float xc[4] = {xv.x, xv.y, xv.z, xv.w};
        #pragma unroll
        for (int c = 0; c < 4; c++) {
            int d = 4 * i + c;
            float4 g0 = gw4[d * 2];
            float4 g1 = gw4[d * 2 + 1];
            s[0] += xc[c] * g0.x; s[1] += xc[c] * g0.y;
            s[2] += xc[c] * g0.z; s[3] += xc[c] * g0.w;
            s[4] += xc[c] * g1.x; s[5] += xc[c] * g1.y;
            s[6] += xc[c] * g1.z; s[7] += xc[c] * g1.w;
        }
    }
    #pragma unroll
    for (int e = 0; e < E_NUM; e++)
        #pragma unroll
        for (int o = 16; o > 0; o >>= 1)
            s[e] += __shfl_xor_sync(0xffffffffu, s[e], o);

    if (lane == 0) {
        float mx = s[0] + gb[0];
        float lg[E_NUM];
        #pragma unroll
        for (int e = 0; e < E_NUM; e++) {
            lg[e] = s[e] + gb[e];
            mx = fmaxf(mx, lg[e]);
        }
        float p[E_NUM], den = 0.f;
        #pragma unroll
        for (int e = 0; e < E_NUM; e++) { p[e] = expf(lg[e] - mx); den += p[e]; }
        float inv = 1.f / den;
        float best = -1.f; int bi = 0;
        #pragma unroll
        for (int e = 0; e < E_NUM; e++) {
            p[e] *= inv;
            g_probs[t * E_NUM + e] = p[e];
            if (p[e] > best) { best = p[e]; bi = e; }
        }
        g_topval[t] = best;
        int slot = atomicAdd(&g_count[bi], 1);
        g_toklist[bi * T_TOKENS + slot] = t;
    }
}

// ---------------- 2/3: tensor-core gathered GEMM ----------------
// 128x256x32 threadblock, 256 threads, warp tile 64x64, 4-stage cp.async
#define BM 128
#define BN 256
#define BK 32
#define STAGES 4
#define A_ROWB  80             // 32 bf16 (64B) padded to 80 B
#define B_ROWB  528            // 256 bf16 (512B) padded to 528 B
#define A_ST    (128 * A_ROWB)            // 10240
#define B_ST    (32 * B_ROWB)             // 16896
#define A_OFF   0
#define B_OFF   (STAGES * A_ST)           // 40960
#define BIAS_OFF (B_OFF + STAGES * B_ST)  // 108544
#define SMEM_BYTES (BIAS_OFF + BN * 4)    // 109568  -> 2 CTAs/SM

// EPI 0: h = gelu(acc + b1) -> g_hb bf16.   EPI 1: y = (acc + b2)*top_val -> g_y f32
template<int KDIM, int NDIM, int EPI>
__global__ __launch_bounds__(256)
void moe_gemm(const __nv_bfloat16* __restrict__ Aglob,
              const __nv_bfloat16* __restrict__ Wglob,
              const float* __restrict__ bias_glob) {
    const int e   = blockIdx.z;
    const int cnt = g_count[e];
    const int m0  = blockIdx.y * BM;
    if (m0 >= cnt) return;
    const int n0  = blockIdx.x * BN;
    const int* toks = g_toklist + e * T_TOKENS;
    const __nv_bfloat16* Bt = Wglob + (size_t)e * KDIM * NDIM;   // [K][N] row-major
    const float* bias = bias_glob + e * NDIM;

    extern __shared__ char dynsm[];
    const uint32_t sb = smem_u32(dynsm);
    float* sbias = (float*)(dynsm + BIAS_OFF);

    const int tid  = threadIdx.x;
    const int lane = tid & 31;
    const int wid  = tid >> 5;
    const int wm   = wid & 1;        // 2 m-slabs of 64 rows
    const int wn   = wid >> 1;       // 4 n-slabs of 64 cols

    sbias[tid] = bias[n0 + tid];

    // ---- A load: row = tid>>1, 2 x 16B units ----
    const int a_row = tid >> 1;
    const int a_u   = (tid & 1) * 2;
    const int gm_a  = m0 + a_row;
    const bool a_ok = (gm_a < cnt);
    const int a_tok = a_ok ? toks[gm_a] : 0;
    const __nv_bfloat16* a_src = Aglob + (size_t)a_tok * KDIM + a_u * 8;
    const int a_bytes = a_ok ? 16 : 0;
    const uint32_t a_loff = a_row * A_ROWB + a_u * 16;

    // ---- B load: rows (tid>>5)+8*i (i=0..3), unit tid&31 ----
    const int b_k  = tid >> 5;           // 0..7
    const int b_nu = tid & 31;
    const __nv_bfloat16* b_src = Bt + (size_t)b_k * NDIM + n0 + b_nu * 8;
    const uint32_t b_loff = b_k * B_ROWB + b_nu * 16;

    float acc[4][8][4];
    #pragma unroll
    for (int i = 0; i < 4; i++)
        #pragma unroll
        for (int j = 0; j < 8; j++)
            #pragma unroll
            for (int c = 0; c < 4; c++) acc[i][j][c] = 0.f;

    // prologue: stages 0..2
    #pragma unroll
    for (int st = 0; st < STAGES - 1; st++) {
        const int ko = st * BK;
        const uint32_t ab = sb + A_OFF + st * A_ST + a_loff;
        const uint32_t bb = sb + B_OFF + st * B_ST + b_loff;
        cp_async16(ab,      a_src + ko,     a_bytes);
        cp_async16(ab + 16, a_src + ko + 8, a_bytes);
        #pragma unroll
        for (int i = 0; i < 4; i++)
            cp_async16(bb + i * 8 * B_ROWB, b_src + (size_t)(ko + 8 * i) * NDIM, 16);
        asm volatile("cp.async.commit_group;\n");
    }

    const int NT = KDIM / BK;
    for (int s = 0; s < NT; s++) {
        asm volatile("cp.async.wait_group %0;\n" :: "n"(STAGES - 2));
        __syncthreads();

        // prefetch stage s+3
        if (s + STAGES - 1 < NT) {
            const int st = (s + STAGES - 1) % STAGES;
            const int ko = (s + STAGES - 1) * BK;
            const uint32_t ab = sb + A_OFF + st * A_ST + a_loff;
            const uint32_t bb = sb + B_OFF + st * B_ST + b_loff;
            cp_async16(ab,      a_src + ko,     a_bytes);
            cp_async16(ab + 16, a_src + ko + 8, a_bytes);
            #pragma unroll
            for (int i = 0; i < 4; i++)
                cp_async16(bb + i * 8 * B_ROWB, b_src + (size_t)(ko + 8 * i) * NDIM, 16);
        }
        asm volatile("cp.async.commit_group;\n");

        const int buf = s % STAGES;
        const uint32_t abase = sb + A_OFF + buf * A_ST;
        const uint32_t bbase = sb + B_OFF + buf * B_ST;
        #pragma unroll
        for (int ks = 0; ks < 2; ks++) {
            uint32_t afr[4][4];
            #pragma unroll
            for (int mt = 0; mt < 4; mt++) {
                int row = wm * 64 + mt * 16 + (lane & 15);
                ldsm_x4(afr[mt], abase + row * A_ROWB + ks * 32 + ((lane >> 4) << 4));
            }
            uint32_t bfr[4][4];
            #pragma unroll
            for (int pr = 0; pr < 4; pr++) {
                int row = ks * 16 + (lane & 15);
                int col = wn * 64 + pr * 16 + ((lane >> 4) << 3);
                ldsm_x4_trans(bfr[pr], bbase + row * B_ROWB + col * 2);
            }
            #pragma unroll
            for (int mt = 0; mt < 4; mt++)
                #pragma unroll
                for (int nt = 0; nt < 8; nt++) {
                    int pr = nt >> 1;
                    int hb = (nt & 1) * 2;
                    mma_bf16(acc[mt][nt], afr[mt], bfr[pr][hb], bfr[pr][hb + 1]);
                }
        }
    }

    // ---- epilogue ----
    #pragma unroll
    for (int mt = 0; mt < 4; mt++) {
        int gm0 = m0 + wm * 64 + mt * 16 + (lane >> 2);
        int gm1 = gm0 + 8;
        bool ok0 = gm0 < cnt, ok1 = gm1 < cnt;
        int tok0 = ok0 ? toks[gm0] : 0;
        int tok1 = ok1 ? toks[gm1] : 0;
        float tv0 = 0.f, tv1 = 0.f;
        if (EPI == 1) {
            tv0 = ok0 ? g_topval[tok0] : 0.f;
            tv1 = ok1 ? g_topval[tok1] : 0.f;
        }
        #pragma unroll
        for (int nt = 0; nt < 8; nt++) {
            int lc = wn * 64 + nt * 8 + (lane & 3) * 2;
            float bv0 = sbias[lc], bv1 = sbias[lc + 1];
            float* a = acc[mt][nt];
            if (EPI == 0) {
                if (ok0) {
                    __nv_bfloat162 v = __floats2bfloat162_rn(
                        gelu_exact(a[0] + bv0), gelu_exact(a[1] + bv1));
                    *(__nv_bfloat162*)(g_hb + (size_t)tok0 * H_DIM + n0 + lc) = v;
                }
                if (ok1) {
                    __nv_bfloat162 v = __floats2bfloat162_rn(
                        gelu_exact(a[2] + bv0), gelu_exact(a[3] + bv1));
                    *(__nv_bfloat162*)(g_hb + (size_t)tok1 * H_DIM + n0 + lc) = v;
                }
            } else {
                if (ok0) {
                    float2 v = make_float2((a[0] + bv0) * tv0, (a[1] + bv1) * tv0);
                    *(float2*)(g_y + (size_t)tok0 * D_DIM + n0 + lc) = v;
                }
                if (ok1) {
                    float2 v = make_float2((a[2] + bv0) * tv1, (a[3] + bv1) * tv1);
                    *(float2*)(g_y + (size_t)tok1 * D_DIM + n0 + lc) = v;
                }
            }
        }
    }
}

// ---------------- 4: residual + L2-normalize + gamma*sqrt(D) + gelu ----------------
__global__ void finalize_kernel(const float* __restrict__ x,
                                const float* __restrict__ gamma,
                                float* __restrict__ out) {
    const int t   = blockIdx.x;
    const int tid = threadIdx.x;
    const float* xr = x  + (size_t)t * D_DIM;
    const float* er = g_y + (size_t)t * D_DIM;
    float yv[4];
    float ss = 0.f;
    #pragma unroll
    for (int i = 0; i < 4; i++) {
        int d = i * 256 + tid;
        float v = xr[d] + er[d];
        yv[i] = v;
        ss += v * v;
    }
    __shared__ float red[256];
    red[tid] = ss;
    __syncthreads();
    #pragma unroll
    for (int o = 128; o > 0; o >>= 1) {
        if (tid < o) red[tid] += red[tid + o];
        __syncthreads();
    }
    float nrm   = sqrtf(red[0]);
    float scale = 32.0f / fmaxf(nrm, 1e-12f);
    float* orow = out + (size_t)t * D_DIM;
    #pragma unroll
    for (int i = 0; i < 4; i++) {
        int d = i * 256 + tid;
        float v = yv[i] * scale * gamma[d];
        orow[d] = gelu_exact(v);
    }
}

// ---------------- 5: load-balance loss ----------------
__global__ void loss_kernel(float* __restrict__ out, int out_size) {
    __shared__ float red[256];
    __shared__ float imp[E_NUM];
    const int tid = threadIdx.x;
    for (int e = 0; e < E_NUM; e++) {
        float s = 0.f;
        for (int t = tid; t < T_TOKENS; t += 256)
            s += g_probs[t * E_NUM + e];
        red[tid] = s;
        __syncthreads();
        #pragma unroll
        for (int o = 128; o > 0; o >>= 1) {
            if (tid < o) red[tid] += red[tid + o];
            __syncthreads();
        }
        if (tid == 0) imp[e] = red[0];
        __syncthreads();
    }
    if (tid == 0) {
        float sum = 0.f;
        #pragma unroll
        for (int e = 0; e < E_NUM; e++) sum += imp[e];
        float mean = sum / (float)E_NUM;
        float var = 0.f;
        #pragma unroll
        for (int e = 0; e < E_NUM; e++) {
            float dlt = imp[e] - mean;
            var += dlt * dlt;
        }
        var /= (float)(E_NUM - 1);
        float loss = var / (mean * mean + 1e-10f);
        if (out_size > T_TOKENS * D_DIM)
            out[T_TOKENS * D_DIM] = loss;
    }
}

// ---------------- launch (stream fork/join, graph-capturable) ----------------
extern "C" void kernel_launch(void* const* d_in, const int* in_sizes, int n_in,
                              void* d_out, int out_size) {
    const float* x     = (const float*)d_in[0];
    const float* gw    = (const float*)d_in[1];
    const float* gb    = (const float*)d_in[2];
    const float* w1    = (const float*)d_in[3];
    const float* b1    = (const float*)d_in[4];
    const float* w2    = (const float*)d_in[5];
    const float* b2    = (const float*)d_in[6];
    const float* gamma = (const float*)d_in[7];
    float* out = (float*)d_out;

    __nv_bfloat16 *xb, *w1b, *w2b, *hb;
    cudaGetSymbolAddress((void**)&xb,  g_xb);
    cudaGetSymbolAddress((void**)&w1b, g_w1b);
    cudaGetSymbolAddress((void**)&w2b, g_w2b);
    cudaGetSymbolAddress((void**)&hb,  g_hb);

    static bool init_done = false;
    static cudaStream_t s1, s2;
    static cudaEvent_t ev_fork, ev_w1, ev_w2;
    if (!init_done) {
        cudaStreamCreateWithFlags(&s1, cudaStreamNonBlocking);
        cudaStreamCreateWithFlags(&s2, cudaStreamNonBlocking);
        cudaEventCreateWithFlags(&ev_fork, cudaEventDisableTiming);
        cudaEventCreateWithFlags(&ev_w1,   cudaEventDisableTiming);
        cudaEventCreateWithFlags(&ev_w2,   cudaEventDisableTiming);
        cudaFuncSetAttribute(moe_gemm<D_DIM, H_DIM, 0>,
                             cudaFuncAttributeMaxDynamicSharedMemorySize, SMEM_BYTES);
        cudaFuncSetAttribute(moe_gemm<H_DIM, D_DIM, 1>,
                             cudaFuncAttributeMaxDynamicSharedMemorySize, SMEM_BYTES);
        init_done = true;
    }

    const int nw = E_NUM * D_DIM * H_DIM;

    // fork: weight converts on side streams
    cudaEventRecord(ev_fork, 0);
    cudaStreamWaitEvent(s1, ev_fork, 0);
    cudaStreamWaitEvent(s2, ev_fork, 0);
    convert_kernel<<<(nw / 4 + 255) / 256, 256, 0, s1>>>(w1, w1b, nw);
    convert_kernel<<<(nw / 4 + 255) / 256, 256, 0, s2>>>(w2, w2b, nw);
    cudaEventRecord(ev_w1, s1);
    cudaEventRecord(ev_w2, s2);

    // main stream: routing-side chain
    zero_kernel<<<1, 32>>>();
    {
        int n = T_TOKENS * D_DIM;
        convert_kernel<<<(n / 4 + 255) / 256, 256>>>(x, xb, n);
    }
    gate_kernel<<<T_TOKENS / 8, 256>>>(x, gw, gb);

    // join w1, run GEMM1
    cudaStreamWaitEvent(0, ev_w1, 0);
    moe_gemm<D_DIM, H_DIM, 0>
        <<<dim3(H_DIM / BN, T_TOKENS / BM, E_NUM), 256, SMEM_BYTES>>>(xb, w1b, b1);

    // join w2, run GEMM2
    cudaStreamWaitEvent(0, ev_w2, 0);
    moe_gemm<H_DIM, D_DIM, 1>
        <<<dim3(D_DIM / BN, T_TOKENS / BM, E_NUM), 256, SMEM_BYTES>>>(hb, w2b, b2);

    finalize_kernel<<<T_TOKENS, 256>>>(x, gamma, out);
    loss_kernel<<<1, 256>>>(out, out_size);
}

// round 10
// speedup vs baseline: 1.1425x; 1.1425x over previous
#include <cuda_runtime.h>
#include <cuda_bf16.h>
#include <math.h>
#include <stdint.h>

#define T_TOKENS 4096
#define D_DIM    1024
#define H_DIM    2048
#define E_NUM    8

// ---------------- scratch (device globals; no runtime allocation) ----------
__device__ float g_probs[T_TOKENS * E_NUM];
__device__ float g_topval[T_TOKENS];
__device__ int   g_count[E_NUM];
__device__ int   g_toklist[E_NUM * T_TOKENS];
__device__ __nv_bfloat16 g_xb[T_TOKENS * D_DIM];          // x bf16 [T,D]
__device__ __nv_bfloat16 g_w1b[E_NUM * D_DIM * H_DIM];    // w1 bf16 [E][D][H]
__device__ __nv_bfloat16 g_w2b[E_NUM * H_DIM * D_DIM];    // w2 bf16 [E][H][D]
__device__ __nv_bfloat16 g_hb[T_TOKENS * H_DIM];          // hidden bf16 [T,H]
__device__ float g_y[T_TOKENS * D_DIM];                   // expert out * top_val

__device__ __forceinline__ float gelu_exact(float v) {
    return 0.5f * v * (1.0f + erff(v * 0.70710678118654752440f));
}

__device__ __forceinline__ uint32_t smem_u32(const void* p) {
    return (uint32_t)__cvta_generic_to_shared(p);
}

__device__ __forceinline__ void cp_async16(uint32_t dst, const void* src, int src_bytes) {
    asm volatile("cp.async.cg.shared.global [%0], [%1], 16, %2;\n"
                 :: "r"(dst), "l"(src), "r"(src_bytes));
}

__device__ __forceinline__ void ldsm_x4(uint32_t* r, uint32_t addr) {
    asm volatile("ldmatrix.sync.aligned.m8n8.x4.shared.b16 {%0,%1,%2,%3}, [%4];\n"
                 : "=r"(r[0]), "=r"(r[1]), "=r"(r[2]), "=r"(r[3]) : "r"(addr));
}

__device__ __forceinline__ void ldsm_x4_trans(uint32_t* r, uint32_t addr) {
    asm volatile("ldmatrix.sync.aligned.m8n8.x4.trans.shared.b16 {%0,%1,%2,%3}, [%4];\n"
                 : "=r"(r[0]), "=r"(r[1]), "=r"(r[2]), "=r"(r[3]) : "r"(addr));
}

__device__ __forceinline__ void mma_bf16(float* d, const uint32_t* a, uint32_t b0, uint32_t b1) {
    asm volatile("mma.sync.aligned.m16n8k16.row.col.f32.bf16.bf16.f32 "
                 "{%0,%1,%2,%3}, {%4,%5,%6,%7}, {%8,%9}, {%0,%1,%2,%3};\n"
                 : "+f"(d[0]), "+f"(d[1]), "+f"(d[2]), "+f"(d[3])
                 : "r"(a[0]), "r"(a[1]), "r"(a[2]), "r"(a[3]), "r"(b0), "r"(b1));
}

// ---------------- 0: zero counters ----------------
__global__ void zero_kernel() {
    if (threadIdx.x < E_NUM) g_count[threadIdx.x] = 0;
}

// ---------------- 0b: fp32 -> bf16 conversion ----------------
__global__ void convert_kernel(const float* __restrict__ src,
                               __nv_bfloat16* __restrict__ dst, int n) {
    int i = (blockIdx.x * blockDim.x + threadIdx.x) * 4;
    if (i < n) {
        float4 v = *(const float4*)(src + i);
        __nv_bfloat162* d = (__nv_bfloat162*)(dst + i);
        d[0] = __floats2bfloat162_rn(v.x, v.y);
        d[1] = __floats2bfloat162_rn(v.z, v.w);
    }
}

// ---------------- 1: gating (one warp per token) ----------------
__global__ void gate_kernel(const float* __restrict__ x,
                            const float* __restrict__ gw,
                            const float* __restrict__ gb) {
    const int warp = threadIdx.x >> 5;
    const int lane = threadIdx.x & 31;
    const int t = blockIdx.x * 8 + warp;
    const float4* xr4 = (const float4*)(x + (size_t)t * D_DIM);
    const float4* gw4 = (const float4*)gw;    // [D][8] -> 2 float4 per d

    float s[E_NUM];
    #pragma unroll
    for (int e = 0; e < E_NUM; e++) s[e] = 0.f;

    #pragma unroll
    for (int j = 0; j < 8; j++) {
        int i = lane + 32 * j;
        float4 xv = xr4[i];
        float xc[4] = {xv.x, xv.y, xv.z, xv.w};
        #pragma unroll
        for (int c = 0; c < 4; c++) {
            int d = 4 * i + c;
            float4 g0 = gw4[d * 2];
            float4 g1 = gw4[d * 2 + 1];
            s[0] += xc[c] * g0.x; s[1] += xc[c] * g0.y;
            s[2] += xc[c] * g0.z; s[3] += xc[c] * g0.w;
            s[4] += xc[c] * g1.x; s[5] += xc[c] * g1.y;
            s[6] += xc[c] * g1.z; s[7] += xc[c] * g1.w;
        }
    }
    #pragma unroll
    for (int e = 0; e < E_NUM; e++)
        #pragma unroll
        for (int o = 16; o > 0; o >>= 1)
            s[e] += __shfl_xor_sync(0xffffffffu, s[e], o);

    if (lane == 0) {
        float mx = s[0] + gb[0];
        float lg[E_NUM];
        #pragma unroll
        for (int e = 0; e < E_NUM; e++) {
            lg[e] = s[e] + gb[e];
            mx = fmaxf(mx, lg[e]);
        }
        float p[E_NUM], den = 0.f;
        #pragma unroll
        for (int e = 0; e < E_NUM; e++) { p[e] = expf(lg[e] - mx); den += p[e]; }
        float inv = 1.f / den;
        float best = -1.f; int bi = 0;
        #pragma unroll
        for (int e = 0; e < E_NUM; e++) {
            p[e] *= inv;
            g_probs[t * E_NUM + e] = p[e];
            if (p[e] > best) { best = p[e]; bi = e; }
        }
        g_topval[t] = best;
        int slot = atomicAdd(&g_count[bi], 1);
        g_toklist[bi * T_TOKENS + slot] = t;
    }
}

// ---------------- 2/3: tensor-core gathered GEMM ----------------
// 128x256x32 threadblock, 512 threads, warp tile 32x64 (low regs -> 16 warps/SM)
#define BM 128
#define BN 256
#define BK 32
#define STAGES 4
#define A_ROWB  80             // 32 bf16 (64B) padded to 80 B
#define B_ROWB  528            // 256 bf16 (512B) padded to 528 B
#define A_ST    (128 * A_ROWB)            // 10240
#define B_ST    (32 * B_ROWB)             // 16896
#define A_OFF   0
#define B_OFF   (STAGES * A_ST)           // 40960
#define BIAS_OFF (B_OFF + STAGES * B_ST)  // 108544
#define SMEM_BYTES (BIAS_OFF + BN * 4)    // 109568

// EPI 0: h = gelu(acc + b1) -> g_hb bf16.   EPI 1: y = (acc + b2)*top_val -> g_y f32
template<int KDIM, int NDIM, int EPI>
__global__ __launch_bounds__(512, 1)
void moe_gemm(const __nv_bfloat16* __restrict__ Aglob,
              const __nv_bfloat16* __restrict__ Wglob,
              const float* __restrict__ bias_glob) {
    const int e   = blockIdx.z;
    const int cnt = g_count[e];
    const int m0  = blockIdx.y * BM;
    if (m0 >= cnt) return;
    const int n0  = blockIdx.x * BN;
    const int* toks = g_toklist + e * T_TOKENS;
    const __nv_bfloat16* Bt = Wglob + (size_t)e * KDIM * NDIM;   // [K][N] row-major
    const float* bias = bias_glob + e * NDIM;

    extern __shared__ char dynsm[];
    const uint32_t sb = smem_u32(dynsm);
    float* sbias = (float*)(dynsm + BIAS_OFF);

    const int tid  = threadIdx.x;
    const int lane = tid & 31;
    const int wid  = tid >> 5;       // 0..15
    const int wm   = wid & 3;        // 4 m-slabs of 32 rows
    const int wn   = wid >> 2;       // 4 n-slabs of 64 cols

    if (tid < BN) sbias[tid] = bias[n0 + tid];

    // ---- A load: 1 x 16B per thread ----
    const int a_row = tid >> 2;          // 0..127
    const int a_u   = tid & 3;
    const int gm_a  = m0 + a_row;
    const bool a_ok = (gm_a < cnt);
    const int a_tok = a_ok ? toks[gm_a] : 0;
    const __nv_bfloat16* a_src = Aglob + (size_t)a_tok * KDIM + a_u * 8;
    const int a_bytes = a_ok ? 16 : 0;
    const uint32_t a_loff = a_row * A_ROWB + a_u * 16;

    // ---- B load: 2 x 16B per thread (rows b_k, b_k+16) ----
    const int b_k  = tid >> 5;           // 0..15
    const int b_nu = tid & 31;
    const __nv_bfloat16* b_src0 = Bt + (size_t)b_k * NDIM + n0 + b_nu * 8;
    const __nv_bfloat16* b_src1 = b_src0 + (size_t)16 * NDIM;
    const uint32_t b_loff0 = b_k * B_ROWB + b_nu * 16;
    const uint32_t b_loff1 = b_loff0 + 16 * B_ROWB;

    float acc[2][8][4];
    #pragma unroll
    for (int i = 0; i < 2; i++)
        #pragma unroll
        for (int j = 0; j < 8; j++)
            #pragma unroll
            for (int c = 0; c < 4; c++) acc[i][j][c] = 0.f;

    // prologue: stages 0..2
    #pragma unroll
    for (int st = 0; st < STAGES - 1; st++) {
        const int ko = st * BK;
        cp_async16(sb + A_OFF + st * A_ST + a_loff,  a_src + ko, a_bytes);
        cp_async16(sb + B_OFF + st * B_ST + b_loff0, b_src0 + (size_t)ko * NDIM, 16);
        cp_async16(sb + B_OFF + st * B_ST + b_loff1, b_src1 + (size_t)ko * NDIM, 16);
        asm volatile("cp.async.commit_group;\n");
    }

    const int NT = KDIM / BK;
    for (int s = 0; s < NT; s++) {
        asm volatile("cp.async.wait_group %0;\n" :: "n"(STAGES - 2));
        __syncthreads();

        // prefetch stage s+3
        if (s + STAGES - 1 < NT) {
            const int st = (s + STAGES - 1) % STAGES;
            const int ko = (s + STAGES - 1) * BK;
            cp_async16(sb + A_OFF + st * A_ST + a_loff,  a_src + ko, a_bytes);
            cp_async16(sb + B_OFF + st * B_ST + b_loff0, b_src0 + (size_t)ko * NDIM, 16);
            cp_async16(sb + B_OFF + st * B_ST + b_loff1, b_src1 + (size_t)ko * NDIM, 16);
        }
        asm volatile("cp.async.commit_group;\n");

        const int buf = s % STAGES;
        const uint32_t abase = sb + A_OFF + buf * A_ST;
        const uint32_t bbase = sb + B_OFF + buf * B_ST;
        #pragma unroll
        for (int ks = 0; ks < 2; ks++) {
            uint32_t afr[2][4];
            #pragma unroll
            for (int mt = 0; mt < 2; mt++) {
                int row = wm * 32 + mt * 16 + (lane & 15);
                ldsm_x4(afr[mt], abase + row * A_ROWB + ks * 32 + ((lane >> 4) << 4));
            }
            uint32_t bfr[4][4];
            #pragma unroll
            for (int pr = 0; pr < 4; pr++) {
                int row = ks * 16 + (lane & 15);
                int col = wn * 64 + pr * 16 + ((lane >> 4) << 3);
                ldsm_x4_trans(bfr[pr], bbase + row * B_ROWB + col * 2);
            }
            #pragma unroll
            for (int mt = 0; mt < 2; mt++)
                #pragma unroll
                for (int nt = 0; nt < 8; nt++) {
                    int pr = nt >> 1;
                    int hb = (nt & 1) * 2;
                    mma_bf16(acc[mt][nt], afr[mt], bfr[pr][hb], bfr[pr][hb + 1]);
                }
        }
    }

    // ---- epilogue ----
    #pragma unroll
    for (int mt = 0; mt < 2; mt++) {
        int gm0 = m0 + wm * 32 + mt * 16 + (lane >> 2);
        int gm1 = gm0 + 8;
        bool ok0 = gm0 < cnt, ok1 = gm1 < cnt;
        int tok0 = ok0 ? toks[gm0] : 0;
        int tok1 = ok1 ? toks[gm1] : 0;
        float tv0 = 0.f, tv1 = 0.f;
        if (EPI == 1) {
            tv0 = ok0 ? g_topval[tok0] : 0.f;
            tv1 = ok1 ? g_topval[tok1] : 0.f;
        }
        #pragma unroll
        for (int nt = 0; nt < 8; nt++) {
            int lc = wn * 64 + nt * 8 + (lane & 3) * 2;
            float bv0 = sbias[lc], bv1 = sbias[lc + 1];
            float* a = acc[mt][nt];
            if (EPI == 0) {
                if (ok0) {
                    __nv_bfloat162 v = __floats2bfloat162_rn(
                        gelu_exact(a[0] + bv0), gelu_exact(a[1] + bv1));
                    *(__nv_bfloat162*)(g_hb + (size_t)tok0 * H_DIM + n0 + lc) = v;
                }
                if (ok1) {
                    __nv_bfloat162 v = __floats2bfloat162_rn(
                        gelu_exact(a[2] + bv0), gelu_exact(a[3] + bv1));
                    *(__nv_bfloat162*)(g_hb + (size_t)tok1 * H_DIM + n0 + lc) = v;
                }
            } else {
                if (ok0) {
                    float2 v = make_float2((a[0] + bv0) * tv0, (a[1] + bv1) * tv0);
                    *(float2*)(g_y + (size_t)tok0 * D_DIM + n0 + lc) = v;
                }
                if (ok1) {
                    float2 v = make_float2((a[2] + bv0) * tv1, (a[3] + bv1) * tv1);
                    *(float2*)(g_y + (size_t)tok1 * D_DIM + n0 + lc) = v;
                }
            }
        }
    }
}

// ---------------- 4: residual + L2-normalize + gamma*sqrt(D) + gelu ----------------
__global__ void finalize_kernel(const float* __restrict__ x,
                                const float* __restrict__ gamma,
                                float* __restrict__ out) {
    const int t   = blockIdx.x;
    const int tid = threadIdx.x;
    const float* xr = x  + (size_t)t * D_DIM;
    const float* er = g_y + (size_t)t * D_DIM;
    float yv[4];
    float ss = 0.f;
    #pragma unroll
    for (int i = 0; i < 4; i++) {
        int d = i * 256 + tid;
        float v = xr[d] + er[d];
        yv[i] = v;
        ss += v * v;
    }
    __shared__ float red[256];
    red[tid] = ss;
    __syncthreads();
    #pragma unroll
    for (int o = 128; o > 0; o >>= 1) {
        if (tid < o) red[tid] += red[tid + o];
        __syncthreads();
    }
    float nrm   = sqrtf(red[0]);
    float scale = 32.0f / fmaxf(nrm, 1e-12f);
    float* orow = out + (size_t)t * D_DIM;
    #pragma unroll
    for (int i = 0; i < 4; i++) {
        int d = i * 256 + tid;
        float v = yv[i] * scale * gamma[d];
        orow[d] = gelu_exact(v);
    }
}

// ---------------- 5: load-balance loss ----------------
__global__ void loss_kernel(float* __restrict__ out, int out_size) {
    __shared__ float red[256];
    __shared__ float imp[E_NUM];
    const int tid = threadIdx.x;
    for (int e = 0; e < E_NUM; e++) {
        float s = 0.f;
        for (int t = tid; t < T_TOKENS; t += 256)
            s += g_probs[t * E_NUM + e];
        red[tid] = s;
        __syncthreads();
        #pragma unroll
        for (int o = 128; o > 0; o >>= 1) {
            if (tid < o) red[tid] += red[tid + o];
            __syncthreads();
        }
        if (tid == 0) imp[e] = red[0];
        __syncthreads();
    }
    if (tid == 0) {
        float sum = 0.f;
        #pragma unroll
        for (int e = 0; e < E_NUM; e++) sum += imp[e];
        float mean = sum / (float)E_NUM;
        float var = 0.f;
        #pragma unroll
        for (int e = 0; e < E_NUM; e++) {
            float dlt = imp[e] - mean;
            var += dlt * dlt;
        }
        var /= (float)(E_NUM - 1);
        float loss = var / (mean * mean + 1e-10f);
        if (out_size > T_TOKENS * D_DIM)
            out[T_TOKENS * D_DIM] = loss;
    }
}

// ---------------- launch (stream fork/join, graph-capturable) ----------------
extern "C" void kernel_launch(void* const* d_in, const int* in_sizes, int n_in,
                              void* d_out, int out_size) {
    const float* x     = (const float*)d_in[0];
    const float* gw    = (const float*)d_in[1];
    const float* gb    = (const float*)d_in[2];
    const float* w1    = (const float*)d_in[3];
    const float* b1    = (const float*)d_in[4];
    const float* w2    = (const float*)d_in[5];
    const float* b2    = (const float*)d_in[6];
    const float* gamma = (const float*)d_in[7];
    float* out = (float*)d_out;

    __nv_bfloat16 *xb, *w1b, *w2b, *hb;
    cudaGetSymbolAddress((void**)&xb,  g_xb);
    cudaGetSymbolAddress((void**)&w1b, g_w1b);
    cudaGetSymbolAddress((void**)&w2b, g_w2b);
    cudaGetSymbolAddress((void**)&hb,  g_hb);

    static bool init_done = false;
    static cudaStream_t s1, s2, s3;
    static cudaEvent_t ev_fork, ev_w1, ev_w2, ev_gate, ev_loss;
    if (!init_done) {
        cudaStreamCreateWithFlags(&s1, cudaStreamNonBlocking);
        cudaStreamCreateWithFlags(&s2, cudaStreamNonBlocking);
        cudaStreamCreateWithFlags(&s3, cudaStreamNonBlocking);
        cudaEventCreateWithFlags(&ev_fork, cudaEventDisableTiming);
        cudaEventCreateWithFlags(&ev_w1,   cudaEventDisableTiming);
        cudaEventCreateWithFlags(&ev_w2,   cudaEventDisableTiming);
        cudaEventCreateWithFlags(&ev_gate, cudaEventDisableTiming);
        cudaEventCreateWithFlags(&ev_loss, cudaEventDisableTiming);
        cudaFuncSetAttribute(moe_gemm<D_DIM, H_DIM, 0>,
                             cudaFuncAttributeMaxDynamicSharedMemorySize, SMEM_BYTES);
        cudaFuncSetAttribute(moe_gemm<H_DIM, D_DIM, 1>,
                             cudaFuncAttributeMaxDynamicSharedMemorySize, SMEM_BYTES);
        init_done = true;
    }

    const int nw = E_NUM * D_DIM * H_DIM;

    // fork
    cudaEventRecord(ev_fork, 0);
    cudaStreamWaitEvent(s1, ev_fork, 0);
    cudaStreamWaitEvent(s2, ev_fork, 0);
    cudaStreamWaitEvent(s3, ev_fork, 0);

    // s1/s2: weight converts
    convert_kernel<<<(nw / 4 + 255) / 256, 256, 0, s1>>>(w1, w1b, nw);
    convert_kernel<<<(nw / 4 + 255) / 256, 256, 0, s2>>>(w2, w2b, nw);
    cudaEventRecord(ev_w1, s1);
    cudaEventRecord(ev_w2, s2);

    // s3: routing chain + loss (loss runs concurrent with GEMMs)
    zero_kernel<<<1, 32, 0, s3>>>();
    gate_kernel<<<T_TOKENS / 8, 256, 0, s3>>>(x, gw, gb);
    cudaEventRecord(ev_gate, s3);
    loss_kernel<<<1, 256, 0, s3>>>(out, out_size);
    cudaEventRecord(ev_loss, s3);

    // main: x convert
    {
        int n = T_TOKENS * D_DIM;
        convert_kernel<<<(n / 4 + 255) / 256, 256>>>(x, xb, n);
    }

    // join gate + w1, run GEMM1
    cudaStreamWaitEvent(0, ev_gate, 0);
    cudaStreamWaitEvent(0, ev_w1, 0);
    moe_gemm<D_DIM, H_DIM, 0>
        <<<dim3(H_DIM / BN, T_TOKENS / BM, E_NUM), 512, SMEM_BYTES>>>(xb, w1b, b1);

    // join w2, run GEMM2
    cudaStreamWaitEvent(0, ev_w2, 0);
    moe_gemm<H_DIM, D_DIM, 1>
        <<<dim3(D_DIM / BN, T_TOKENS / BM, E_NUM), 512, SMEM_BYTES>>>(hb, w2b, b2);

    finalize_kernel<<<T_TOKENS, 256>>>(x, gamma, out);
    cudaStreamWaitEvent(0, ev_loss, 0);
}

// round 11
// speedup vs baseline: 1.2688x; 1.1106x over previous
#include <cuda_runtime.h>
#include <cuda_bf16.h>
#include <math.h>
#include <stdint.h>

#define T_TOKENS 4096
#define D_DIM    1024
#define H_DIM    2048
#define E_NUM    8

// ---------------- scratch (device globals; no runtime allocation) ----------
__device__ float g_probs[T_TOKENS * E_NUM];
__device__ float g_topval[T_TOKENS];
__device__ int   g_count[E_NUM];
__device__ int   g_toklist[E_NUM * T_TOKENS];
__device__ __nv_bfloat16 g_xb[T_TOKENS * D_DIM];          // x bf16 [T,D]
__device__ __nv_bfloat16 g_w1b[E_NUM * D_DIM * H_DIM];    // w1 bf16 [E][D][H]
__device__ __nv_bfloat16 g_w2b[E_NUM * H_DIM * D_DIM];    // w2 bf16 [E][H][D]
__device__ __nv_bfloat16 g_hb[T_TOKENS * H_DIM];          // hidden bf16 [T,H]
__device__ float g_y[T_TOKENS * D_DIM];                   // expert out * top_val

__device__ __forceinline__ float gelu_exact(float v) {
    return 0.5f * v * (1.0f + erff(v * 0.70710678118654752440f));
}

__device__ __forceinline__ uint32_t smem_u32(const void* p) {
    return (uint32_t)__cvta_generic_to_shared(p);
}

__device__ __forceinline__ void cp_async16(uint32_t dst, const void* src, int src_bytes) {
    asm volatile("cp.async.cg.shared.global [%0], [%1], 16, %2;\n"
                 :: "r"(dst), "l"(src), "r"(src_bytes));
}

__device__ __forceinline__ void ldsm_x4(uint32_t* r, uint32_t addr) {
    asm volatile("ldmatrix.sync.aligned.m8n8.x4.shared.b16 {%0,%1,%2,%3}, [%4];\n"
                 : "=r"(r[0]), "=r"(r[1]), "=r"(r[2]), "=r"(r[3]) : "r"(addr));
}

__device__ __forceinline__ void ldsm_x4_trans(uint32_t* r, uint32_t addr) {
    asm volatile("ldmatrix.sync.aligned.m8n8.x4.trans.shared.b16 {%0,%1,%2,%3}, [%4];\n"
                 : "=r"(r[0]), "=r"(r[1]), "=r"(r[2]), "=r"(r[3]) : "r"(addr));
}

__device__ __forceinline__ void mma_bf16(float* d, const uint32_t* a, uint32_t b0, uint32_t b1) {
    asm volatile("mma.sync.aligned.m16n8k16.row.col.f32.bf16.bf16.f32 "
                 "{%0,%1,%2,%3}, {%4,%5,%6,%7}, {%8,%9}, {%0,%1,%2,%3};\n"
                 : "+f"(d[0]), "+f"(d[1]), "+f"(d[2]), "+f"(d[3])
                 : "r"(a[0]), "r"(a[1]), "r"(a[2]), "r"(a[3]), "r"(b0), "r"(b1));
}

// ---------------- 0: zero counters ----------------
__global__ void zero_kernel() {
    if (threadIdx.x < E_NUM) g_count[threadIdx.x] = 0;
}

// ---------------- 0b: fp32 -> bf16 conversion ----------------
__global__ void convert_kernel(const float* __restrict__ src,
                               __nv_bfloat16* __restrict__ dst, int n) {
    int i = (blockIdx.x * blockDim.x + threadIdx.x) * 4;
    if (i < n) {
        float4 v = *(const float4*)(src + i);
        __nv_bfloat162* d = (__nv_bfloat162*)(dst + i);
        d[0] = __floats2bfloat162_rn(v.x, v.y);
        d[1] = __floats2bfloat162_rn(v.z, v.w);
    }
}

// ---------------- 1: gating (smem-cached gw, 4 tokens per warp) ----------------
// grid = T_TOKENS/32 blocks of 256 threads; block caches gw^T [8][1024] in smem
__global__ __launch_bounds__(256)
void gate_kernel(const float* __restrict__ x,
                 const float* __restrict__ gw,
                 const float* __restrict__ gb) {
    __shared__ float sgw[E_NUM * D_DIM];     // 32 KB, transposed [e][d]
    const int tid = threadIdx.x;

    // load + transpose gw [1024][8] -> sgw [8][1024]
    #pragma unroll
    for (int k = 0; k < 4; k++) {
        int d = tid + 256 * k;
        float4 q0 = *(const float4*)(gw + d * 8);
        float4 q1 = *(const float4*)(gw + d * 8 + 4);
        sgw[0 * D_DIM + d] = q0.x; sgw[1 * D_DIM + d] = q0.y;
        sgw[2 * D_DIM + d] = q0.z; sgw[3 * D_DIM + d] = q0.w;
        sgw[4 * D_DIM + d] = q1.x; sgw[5 * D_DIM + d] = q1.y;
        sgw[6 * D_DIM + d] = q1.z; sgw[7 * D_DIM + d] = q1.w;
    }
    __syncthreads();

    const int warp = tid >> 5;
    const int lane = tid & 31;

    #pragma unroll
    for (int tt = 0; tt < 4; tt++) {
        const int t = blockIdx.x * 32 + warp * 4 + tt;
        const float4* xr4 = (const float4*)(x + (size_t)t * D_DIM);

        float s[E_NUM];
        #pragma unroll
        for (int e = 0; e < E_NUM; e++) s[e] = 0.f;

        #pragma unroll
        for (int j = 0; j < 8; j++) {
            int i = lane + 32 * j;               // float4 index into row
            float4 xv = xr4[i];
            #pragma unroll
            for (int e = 0; e < E_NUM; e++) {
                float4 g = *(const float4*)(sgw + e * D_DIM + 4 * i);
                s[e] += xv.x * g.x + xv.y * g.y + xv.z * g.z + xv.w * g.w;
            }
        }
        #pragma unroll
        for (int e = 0; e < E_NUM; e++)
            #pragma unroll
            for (int o = 16; o > 0; o >>= 1)
                s[e] += __shfl_xor_sync(0xffffffffu, s[e], o);

        if (lane == 0) {
            float mx = s[0] + gb[0];
            float lg[E_NUM];
            #pragma unroll
            for (int e = 0; e < E_NUM; e++) {
                lg[e] = s[e] + gb[e];
                mx = fmaxf(mx, lg[e]);
            }
            float p[E_NUM], den = 0.f;
            #pragma unroll
            for (int e = 0; e < E_NUM; e++) { p[e] = expf(lg[e] - mx); den += p[e]; }
            float inv = 1.f / den;
            float best = -1.f; int bi = 0;
            #pragma unroll
            for (int e = 0; e < E_NUM; e++) {
                p[e] *= inv;
                g_probs[t * E_NUM + e] = p[e];
                if (p[e] > best) { best = p[e]; bi = e; }
            }
            g_topval[t] = best;
            int slot = atomicAdd(&g_count[bi], 1);
            g_toklist[bi * T_TOKENS + slot] = t;
        }
    }
}

// ---------------- 2/3: tensor-core gathered GEMM ----------------
// 128x256x32 threadblock, 512 threads, warp tile 32x64 (low regs -> 16 warps/SM)
#define BM 128
#define BN 256
#define BK 32
#define STAGES 4
#define A_ROWB  80             // 32 bf16 (64B) padded to 80 B
#define B_ROWB  528            // 256 bf16 (512B) padded to 528 B
#define A_ST    (128 * A_ROWB)            // 10240
#define B_ST    (32 * B_ROWB)             // 16896
#define A_OFF   0
#define B_OFF   (STAGES * A_ST)           // 40960
#define BIAS_OFF (B_OFF + STAGES * B_ST)  // 108544
#define SMEM_BYTES (BIAS_OFF + BN * 4)    // 109568

// EPI 0: h = gelu(acc + b1) -> g_hb bf16.   EPI 1: y = (acc + b2)*top_val -> g_y f32
template<int KDIM, int NDIM, int EPI>
__global__ __launch_bounds__(512, 1)
void moe_gemm(const __nv_bfloat16* __restrict__ Aglob,
              const __nv_bfloat16* __restrict__ Wglob,
              const float* __restrict__ bias_glob) {
    const int e   = blockIdx.z;
    const int cnt = g_count[e];
    const int m0  = blockIdx.y * BM;
    if (m0 >= cnt) return;
    const int n0  = blockIdx.x * BN;
    const int* toks = g_toklist + e * T_TOKENS;
    const __nv_bfloat16* Bt = Wglob + (size_t)e * KDIM * NDIM;   // [K][N] row-major
    const float* bias = bias_glob + e * NDIM;

    extern __shared__ char dynsm[];
    const uint32_t sb = smem_u32(dynsm);
    float* sbias = (float*)(dynsm + BIAS_OFF);

    const int tid  = threadIdx.x;
    const int lane = tid & 31;
    const int wid  = tid >> 5;       // 0..15
    const int wm   = wid & 3;        // 4 m-slabs of 32 rows
    const int wn   = wid >> 2;       // 4 n-slabs of 64 cols

    if (tid < BN) sbias[tid] = bias[n0 + tid];

    // ---- A load: 1 x 16B per thread ----
    const int a_row = tid >> 2;          // 0..127
    const int a_u   = tid & 3;
    const int gm_a  = m0 + a_row;
    const bool a_ok = (gm_a < cnt);
    const int a_tok = a_ok ? toks[gm_a] : 0;
    const __nv_bfloat16* a_src = Aglob + (size_t)a_tok * KDIM + a_u * 8;
    const int a_bytes = a_ok ? 16 : 0;
    const uint32_t a_loff = a_row * A_ROWB + a_u * 16;

    // ---- B load: 2 x 16B per thread (rows b_k, b_k+16) ----
    const int b_k  = tid >> 5;           // 0..15
    const int b_nu = tid & 31;
    const __nv_bfloat16* b_src0 = Bt + (size_t)b_k * NDIM + n0 + b_nu * 8;
    const __nv_bfloat16* b_src1 = b_src0 + (size_t)16 * NDIM;
    const uint32_t b_loff0 = b_k * B_ROWB + b_nu * 16;
    const uint32_t b_loff1 = b_loff0 + 16 * B_ROWB;

    float acc[2][8][4];
    #pragma unroll
    for (int i = 0; i < 2; i++)
        #pragma unroll
        for (int j = 0; j < 8; j++)
            #pragma unroll
            for (int c = 0; c < 4; c++) acc[i][j][c] = 0.f;

    // prologue: stages 0..2
    #pragma unroll
    for (int st = 0; st < STAGES - 1; st++) {
        const int ko = st * BK;
        cp_async16(sb + A_OFF + st * A_ST + a_loff,  a_src + ko, a_bytes);
        cp_async16(sb + B_OFF + st * B_ST + b_loff0, b_src0 + (size_t)ko * NDIM, 16);
        cp_async16(sb + B_OFF + st * B_ST + b_loff1, b_src1 + (size_t)ko * NDIM, 16);
        asm volatile("cp.async.commit_group;\n");
    }

    const int NT = KDIM / BK;
    for (int s = 0; s < NT; s++) {
        asm volatile("cp.async.wait_group %0;\n" :: "n"(STAGES - 2));
        __syncthreads();

        // prefetch stage s+3
        if (s + STAGES - 1 < NT) {
            const int st = (s + STAGES - 1) % STAGES;
            const int ko = (s + STAGES - 1) * BK;
            cp_async16(sb + A_OFF + st * A_ST + a_loff,  a_src + ko, a_bytes);
            cp_async16(sb + B_OFF + st * B_ST + b_loff0, b_src0 + (size_t)ko * NDIM, 16);
            cp_async16(sb + B_OFF + st * B_ST + b_loff1, b_src1 + (size_t)ko * NDIM, 16);
        }
        asm volatile("cp.async.commit_group;\n");

        const int buf = s % STAGES;
        const uint32_t abase = sb + A_OFF + buf * A_ST;
        const uint32_t bbase = sb + B_OFF + buf * B_ST;
        #pragma unroll
        for (int ks = 0; ks < 2; ks++) {
            uint32_t afr[2][4];
            #pragma unroll
            for (int mt = 0; mt < 2; mt++) {
                int row = wm * 32 + mt * 16 + (lane & 15);
                ldsm_x4(afr[mt], abase + row * A_ROWB + ks * 32 + ((lane >> 4) << 4));
            }
            uint32_t bfr[4][4];
            #pragma unroll
            for (int pr = 0; pr < 4; pr++) {
                int row = ks * 16 + (lane & 15);
                int col = wn * 64 + pr * 16 + ((lane >> 4) << 3);
                ldsm_x4_trans(bfr[pr], bbase + row * B_ROWB + col * 2);
            }
            #pragma unroll
            for (int mt = 0; mt < 2; mt++)
                #pragma unroll
                for (int nt = 0; nt < 8; nt++) {
                    int pr = nt >> 1;
                    int hb = (nt & 1) * 2;
                    mma_bf16(acc[mt][nt], afr[mt], bfr[pr][hb], bfr[pr][hb + 1]);
                }
        }
    }

    // ---- epilogue ----
    #pragma unroll
    for (int mt = 0; mt < 2; mt++) {
        int gm0 = m0 + wm * 32 + mt * 16 + (lane >> 2);
        int gm1 = gm0 + 8;
        bool ok0 = gm0 < cnt, ok1 = gm1 < cnt;
        int tok0 = ok0 ? toks[gm0] : 0;
        int tok1 = ok1 ? toks[gm1] : 0;
        float tv0 = 0.f, tv1 = 0.f;
        if (EPI == 1) {
            tv0 = ok0 ? g_topval[tok0] : 0.f;
            tv1 = ok1 ? g_topval[tok1] : 0.f;
        }
        #pragma unroll
        for (int nt = 0; nt < 8; nt++) {
            int lc = wn * 64 + nt * 8 + (lane & 3) * 2;
            float bv0 = sbias[lc], bv1 = sbias[lc + 1];
            float* a = acc[mt][nt];
            if (EPI == 0) {
                if (ok0) {
                    __nv_bfloat162 v = __floats2bfloat162_rn(
                        gelu_exact(a[0] + bv0), gelu_exact(a[1] + bv1));
                    *(__nv_bfloat162*)(g_hb + (size_t)tok0 * H_DIM + n0 + lc) = v;
                }
                if (ok1) {
                    __nv_bfloat162 v = __floats2bfloat162_rn(
                        gelu_exact(a[2] + bv0), gelu_exact(a[3] + bv1));
                    *(__nv_bfloat162*)(g_hb + (size_t)tok1 * H_DIM + n0 + lc) = v;
                }
            } else {
                if (ok0) {
                    float2 v = make_float2((a[0] + bv0) * tv0, (a[1] + bv1) * tv0);
                    *(float2*)(g_y + (size_t)tok0 * D_DIM + n0 + lc) = v;
                }
                if (ok1) {
                    float2 v = make_float2((a[2] + bv0) * tv1, (a[3] + bv1) * tv1);
                    *(float2*)(g_y + (size_t)tok1 * D_DIM + n0 + lc) = v;
                }
            }
        }
    }
}

// ---------------- 4: residual + L2-normalize + gamma*sqrt(D) + gelu ----------------
__global__ void finalize_kernel(const float* __restrict__ x,
                                const float* __restrict__ gamma,
                                float* __restrict__ out) {
    const int t   = blockIdx.x;
    const int tid = threadIdx.x;
    const float* xr = x  + (size_t)t * D_DIM;
    const float* er = g_y + (size_t)t * D_DIM;
    float yv[4];
    float ss = 0.f;
    #pragma unroll
    for (int i = 0; i < 4; i++) {
        int d = i * 256 + tid;
        float v = xr[d] + er[d];
        yv[i] = v;
        ss += v * v;
    }
    __shared__ float red[256];
    red[tid] = ss;
    __syncthreads();
    #pragma unroll
    for (int o = 128; o > 0; o >>= 1) {
        if (tid < o) red[tid] += red[tid + o];
        __syncthreads();
    }
    float nrm   = sqrtf(red[0]);
    float scale = 32.0f / fmaxf(nrm, 1e-12f);
    float* orow = out + (size_t)t * D_DIM;
    #pragma unroll
    for (int i = 0; i < 4; i++) {
        int d = i * 256 + tid;
        float v = yv[i] * scale * gamma[d];
        orow[d] = gelu_exact(v);
    }
}

// ---------------- 5: load-balance loss ----------------
__global__ void loss_kernel(float* __restrict__ out, int out_size) {
    __shared__ float red[256];
    __shared__ float imp[E_NUM];
    const int tid = threadIdx.x;
    for (int e = 0; e < E_NUM; e++) {
        float s = 0.f;
        for (int t = tid; t < T_TOKENS; t += 256)
            s += g_probs[t * E_NUM + e];
        red[tid] = s;
        __syncthreads();
        #pragma unroll
        for (int o = 128; o > 0; o >>= 1) {
            if (tid < o) red[tid] += red[tid + o];
            __syncthreads();
        }
        if (tid == 0) imp[e] = red[0];
        __syncthreads();
    }
    if (tid == 0) {
        float sum = 0.f;
        #pragma unroll
        for (int e = 0; e < E_NUM; e++) sum += imp[e];
        float mean = sum / (float)E_NUM;
        float var = 0.f;
        #pragma unroll
        for (int e = 0; e < E_NUM; e++) {
            float dlt = imp[e] - mean;
            var += dlt * dlt;
        }
        var /= (float)(E_NUM - 1);
        float loss = var / (mean * mean + 1e-10f);
        if (out_size > T_TOKENS * D_DIM)
            out[T_TOKENS * D_DIM] = loss;
    }
}

// ---------------- launch (stream fork/join, graph-capturable) ----------------
extern "C" void kernel_launch(void* const* d_in, const int* in_sizes, int n_in,
                              void* d_out, int out_size) {
    const float* x     = (const float*)d_in[0];
    const float* gw    = (const float*)d_in[1];
    const float* gb    = (const float*)d_in[2];
    const float* w1    = (const float*)d_in[3];
    const float* b1    = (const float*)d_in[4];
    const float* w2    = (const float*)d_in[5];
    const float* b2    = (const float*)d_in[6];
    const float* gamma = (const float*)d_in[7];
    float* out = (float*)d_out;

    __nv_bfloat16 *xb, *w1b, *w2b, *hb;
    cudaGetSymbolAddress((void**)&xb,  g_xb);
    cudaGetSymbolAddress((void**)&w1b, g_w1b);
    cudaGetSymbolAddress((void**)&w2b, g_w2b);
    cudaGetSymbolAddress((void**)&hb,  g_hb);

    static bool init_done = false;
    static cudaStream_t s1, s2, s3;
    static cudaEvent_t ev_fork, ev_w1, ev_w2, ev_gate, ev_loss;
    if (!init_done) {
        cudaStreamCreateWithFlags(&s1, cudaStreamNonBlocking);
        cudaStreamCreateWithFlags(&s2, cudaStreamNonBlocking);
        cudaStreamCreateWithFlags(&s3, cudaStreamNonBlocking);
        cudaEventCreateWithFlags(&ev_fork, cudaEventDisableTiming);
        cudaEventCreateWithFlags(&ev_w1,   cudaEventDisableTiming);
        cudaEventCreateWithFlags(&ev_w2,   cudaEventDisableTiming);
        cudaEventCreateWithFlags(&ev_gate, cudaEventDisableTiming);
        cudaEventCreateWithFlags(&ev_loss, cudaEventDisableTiming);
        cudaFuncSetAttribute(moe_gemm<D_DIM, H_DIM, 0>,
                             cudaFuncAttributeMaxDynamicSharedMemorySize, SMEM_BYTES);
        cudaFuncSetAttribute(moe_gemm<H_DIM, D_DIM, 1>,
                             cudaFuncAttributeMaxDynamicSharedMemorySize, SMEM_BYTES);
        init_done = true;
    }

    const int nw = E_NUM * D_DIM * H_DIM;

    // fork
    cudaEventRecord(ev_fork, 0);
    cudaStreamWaitEvent(s1, ev_fork, 0);
    cudaStreamWaitEvent(s2, ev_fork, 0);
    cudaStreamWaitEvent(s3, ev_fork, 0);

    // s1/s2: weight converts
    convert_kernel<<<(nw / 4 + 255) / 256, 256, 0, s1>>>(w1, w1b, nw);
    convert_kernel<<<(nw / 4 + 255) / 256, 256, 0, s2>>>(w2, w2b, nw);
    cudaEventRecord(ev_w1, s1);
    cudaEventRecord(ev_w2, s2);

    // s3: routing chain + loss (loss runs concurrent with GEMMs)
    zero_kernel<<<1, 32, 0, s3>>>();
    gate_kernel<<<T_TOKENS / 32, 256, 0, s3>>>(x, gw, gb);
    cudaEventRecord(ev_gate, s3);
    loss_kernel<<<1, 256, 0, s3>>>(out, out_size);
    cudaEventRecord(ev_loss, s3);

    // main: x convert
    {
        int n = T_TOKENS * D_DIM;
        convert_kernel<<<(n / 4 + 255) / 256, 256>>>(x, xb, n);
    }

    // join gate + w1, run GEMM1
    cudaStreamWaitEvent(0, ev_gate, 0);
    cudaStreamWaitEvent(0, ev_w1, 0);
    moe_gemm<D_DIM, H_DIM, 0>
        <<<dim3(H_DIM / BN, T_TOKENS / BM, E_NUM), 512, SMEM_BYTES>>>(xb, w1b, b1);

    // join w2, run GEMM2
    cudaStreamWaitEvent(0, ev_w2, 0);
    moe_gemm<H_DIM, D_DIM, 1>
        <<<dim3(D_DIM / BN, T_TOKENS / BM, E_NUM), 512, SMEM_BYTES>>>(hb, w2b, b2);

    finalize_kernel<<<T_TOKENS, 256>>>(x, gamma, out);
    cudaStreamWaitEvent(0, ev_loss, 0);
}

// round 14
// speedup vs baseline: 1.3076x; 1.0305x over previous
#include <cuda_runtime.h>
#include <cuda_bf16.h>
#include <math.h>
#include <stdint.h>

#define T_TOKENS 4096
#define D_DIM    1024
#define H_DIM    2048
#define E_NUM    8

// ---------------- scratch (device globals; no runtime allocation) ----------
__device__ float g_probs[T_TOKENS * E_NUM];
__device__ float g_topval[T_TOKENS];
__device__ int   g_count[E_NUM];
__device__ int   g_toklist[E_NUM * T_TOKENS];
__device__ __nv_bfloat16 g_xb[T_TOKENS * D_DIM];          // x bf16 [T,D]
__device__ __nv_bfloat16 g_w1b[E_NUM * D_DIM * H_DIM];    // w1 bf16 [E][D][H]
__device__ __nv_bfloat16 g_w2b[E_NUM * H_DIM * D_DIM];    // w2 bf16 [E][H][D]
__device__ __nv_bfloat16 g_hb[T_TOKENS * H_DIM];          // hidden bf16 [T,H]
__device__ float g_y[T_TOKENS * D_DIM];                   // expert out * top_val

__device__ __forceinline__ float gelu_exact(float v) {
    return 0.5f * v * (1.0f + erff(v * 0.70710678118654752440f));
}

__device__ __forceinline__ uint32_t smem_u32(const void* p) {
    return (uint32_t)__cvta_generic_to_shared(p);
}

__device__ __forceinline__ void cp_async16(uint32_t dst, const void* src, int src_bytes) {
    asm volatile("cp.async.cg.shared.global [%0], [%1], 16, %2;\n"
                 :: "r"(dst), "l"(src), "r"(src_bytes));
}

__device__ __forceinline__ void ldsm_x4(uint32_t* r, uint32_t addr) {
    asm volatile("ldmatrix.sync.aligned.m8n8.x4.shared.b16 {%0,%1,%2,%3}, [%4];\n"
                 : "=r"(r[0]), "=r"(r[1]), "=r"(r[2]), "=r"(r[3]) : "r"(addr));
}

__device__ __forceinline__ void ldsm_x4_trans(uint32_t* r, uint32_t addr) {
    asm volatile("ldmatrix.sync.aligned.m8n8.x4.trans.shared.b16 {%0,%1,%2,%3}, [%4];\n"
                 : "=r"(r[0]), "=r"(r[1]), "=r"(r[2]), "=r"(r[3]) : "r"(addr));
}

__device__ __forceinline__ void mma_bf16(float* d, const uint32_t* a, uint32_t b0, uint32_t b1) {
    asm volatile("mma.sync.aligned.m16n8k16.row.col.f32.bf16.bf16.f32 "
                 "{%0,%1,%2,%3}, {%4,%5,%6,%7}, {%8,%9}, {%0,%1,%2,%3};\n"
                 : "+f"(d[0]), "+f"(d[1]), "+f"(d[2]), "+f"(d[3])
                 : "r"(a[0]), "r"(a[1]), "r"(a[2]), "r"(a[3]), "r"(b0), "r"(b1));
}

// ---------------- 0: zero counters ----------------
__global__ void zero_kernel() {
    if (threadIdx.x < E_NUM) g_count[threadIdx.x] = 0;
}

// ---------------- 0b: fp32 -> bf16 conversion ----------------
__global__ void convert_kernel(const float* __restrict__ src,
                               __nv_bfloat16* __restrict__ dst, int n) {
    int i = (blockIdx.x * blockDim.x + threadIdx.x) * 4;
    if (i < n) {
        float4 v = *(const float4*)(src + i);
        __nv_bfloat162* d = (__nv_bfloat162*)(dst + i);
        d[0] = __floats2bfloat162_rn(v.x, v.y);
        d[1] = __floats2bfloat162_rn(v.z, v.w);
    }
}

// ---------------- 1: gating (smem-cached gw, 1 token per warp) ----------------
// grid = T_TOKENS/8 blocks of 256 threads; block caches gw^T [8][1024] in smem
__global__ __launch_bounds__(256)
void gate_kernel(const float* __restrict__ x,
                 const float* __restrict__ gw,
                 const float* __restrict__ gb) {
    __shared__ float sgw[E_NUM * D_DIM];     // 32 KB, transposed [e][d]
    const int tid = threadIdx.x;

    // load + transpose gw [1024][8] -> sgw [8][1024]
    #pragma unroll
    for (int k = 0; k < 4; k++) {
        int d = tid + 256 * k;
        float4 q0 = *(const float4*)(gw + d * 8);
        float4 q1 = *(const float4*)(gw + d * 8 + 4);
        sgw[0 * D_DIM + d] = q0.x; sgw[1 * D_DIM + d] = q0.y;
        sgw[2 * D_DIM + d] = q0.z; sgw[3 * D_DIM + d] = q0.w;
        sgw[4 * D_DIM + d] = q1.x; sgw[5 * D_DIM + d] = q1.y;
        sgw[6 * D_DIM + d] = q1.z; sgw[7 * D_DIM + d] = q1.w;
    }
    __syncthreads();

    const int warp = tid >> 5;
    const int lane = tid & 31;
    const int t = blockIdx.x * 8 + warp;
    const float4* xr4 = (const float4*)(x + (size_t)t * D_DIM);

    float s[E_NUM];
    #pragma unroll
    for (int e = 0; e < E_NUM; e++) s[e] = 0.f;

    #pragma unroll
    for (int j = 0; j < 8; j++) {
        int i = lane + 32 * j;               // float4 index into row
        float4 xv = xr4[i];
        #pragma unroll
        for (int e = 0; e < E_NUM; e++) {
            float4 g = *(const float4*)(sgw + e * D_DIM + 4 * i);
            s[e] += xv.x * g.x + xv.y * g.y + xv.z * g.z + xv.w * g.w;
        }
    }
    #pragma unroll
    for (int e = 0; e < E_NUM; e++)
        #pragma unroll
        for (int o = 16; o > 0; o >>= 1)
            s[e] += __shfl_xor_sync(0xffffffffu, s[e], o);

    if (lane == 0) {
        float mx = s[0] + gb[0];
        float lg[E_NUM];
        #pragma unroll
        for (int e = 0; e < E_NUM; e++) {
            lg[e] = s[e] + gb[e];
            mx = fmaxf(mx, lg[e]);
        }
        float p[E_NUM], den = 0.f;
        #pragma unroll
        for (int e = 0; e < E_NUM; e++) { p[e] = expf(lg[e] - mx); den += p[e]; }
        float inv = 1.f / den;
        float best = -1.f; int bi = 0;
        #pragma unroll
        for (int e = 0; e < E_NUM; e++) {
            p[e] *= inv;
            g_probs[t * E_NUM + e] = p[e];
            if (p[e] > best) { best = p[e]; bi = e; }
        }
        g_topval[t] = best;
        int slot = atomicAdd(&g_count[bi], 1);
        g_toklist[bi * T_TOKENS + slot] = t;
    }
}

// ---------------- 2/3: tensor-core gathered GEMM (expert-group launch) ----------------
// 128x256x32 threadblock, 512 threads, warp tile 32x64
#define BM 128
#define BN 256
#define BK 32
#define STAGES 4
#define A_ROWB  80             // 32 bf16 (64B) padded to 80 B
#define B_ROWB  528            // 256 bf16 (512B) padded to 528 B
#define A_ST    (128 * A_ROWB)            // 10240
#define B_ST    (32 * B_ROWB)             // 16896
#define A_OFF   0
#define B_OFF   (STAGES * A_ST)           // 40960
#define BIAS_OFF (B_OFF + STAGES * B_ST)  // 108544
#define SMEM_BYTES (BIAS_OFF + BN * 4)    // 109568

// EPI 0: h = gelu(acc + b1) -> g_hb bf16.   EPI 1: y = (acc + b2)*top_val -> g_y f32
template<int KDIM, int NDIM, int EPI>
__global__ __launch_bounds__(512, 1)
void moe_gemm(const __nv_bfloat16* __restrict__ Aglob,
              const __nv_bfloat16* __restrict__ Wglob,
              const float* __restrict__ bias_glob, int e_base) {
    const int e   = e_base + blockIdx.z;
    const int cnt = g_count[e];
    const int m0  = blockIdx.y * BM;
    if (m0 >= cnt) return;
    const int n0  = blockIdx.x * BN;
    const int* toks = g_toklist + e * T_TOKENS;
    const __nv_bfloat16* Bt = Wglob + (size_t)e * KDIM * NDIM;   // [K][N] row-major
    const float* bias = bias_glob + e * NDIM;

    extern __shared__ char dynsm[];
    const uint32_t sb = smem_u32(dynsm);
    float* sbias = (float*)(dynsm + BIAS_OFF);

    const int tid  = threadIdx.x;
    const int lane = tid & 31;
    const int wid  = tid >> 5;       // 0..15
    const int wm   = wid & 3;        // 4 m-slabs of 32 rows
    const int wn   = wid >> 2;       // 4 n-slabs of 64 cols

    if (tid < BN) sbias[tid] = bias[n0 + tid];

    // ---- A load: 1 x 16B per thread ----
    const int a_row = tid >> 2;          // 0..127
    const int a_u   = tid & 3;
    const int gm_a  = m0 + a_row;
    const bool a_ok = (gm_a < cnt);
    const int a_tok = a_ok ? toks[gm_a] : 0;
    const __nv_bfloat16* a_src = Aglob + (size_t)a_tok * KDIM + a_u * 8;
    const int a_bytes = a_ok ? 16 : 0;
    const uint32_t a_loff = a_row * A_ROWB + a_u * 16;

    // ---- B load: 2 x 16B per thread (rows b_k, b_k+16) ----
    const int b_k  = tid >> 5;           // 0..15
    const int b_nu = tid & 31;
    const __nv_bfloat16* b_src0 = Bt + (size_t)b_k * NDIM + n0 + b_nu * 8;
    const __nv_bfloat16* b_src1 = b_src0 + (size_t)16 * NDIM;
    const uint32_t b_loff0 = b_k * B_ROWB + b_nu * 16;
    const uint32_t b_loff1 = b_loff0 + 16 * B_ROWB;

    float acc[2][8][4];
    #pragma unroll
    for (int i = 0; i < 2; i++)
        #pragma unroll
        for (int j = 0; j < 8; j++)
            #pragma unroll
            for (int c = 0; c < 4; c++) acc[i][j][c] = 0.f;

    // prologue: stages 0..2
    #pragma unroll
    for (int st = 0; st < STAGES - 1; st++) {
        const int ko = st * BK;
        cp_async16(sb + A_OFF + st * A_ST + a_loff,  a_src + ko, a_bytes);
        cp_async16(sb + B_OFF + st * B_ST + b_loff0, b_src0 + (size_t)ko * NDIM, 16);
        cp_async16(sb + B_OFF + st * B_ST + b_loff1, b_src1 + (size_t)ko * NDIM, 16);
        asm volatile("cp.async.commit_group;\n");
    }

    const int NT = KDIM / BK;
    for (int s = 0; s < NT; s++) {
        asm volatile("cp.async.wait_group %0;\n" :: "n"(STAGES - 2));
        __syncthreads();

        // prefetch stage s+3
        if (s + STAGES - 1 < NT) {
            const int st = (s + STAGES - 1) % STAGES;
            const int ko = (s + STAGES - 1) * BK;
            cp_async16(sb + A_OFF + st * A_ST + a_loff,  a_src + ko, a_bytes);
            cp_async16(sb + B_OFF + st * B_ST + b_loff0, b_src0 + (size_t)ko * NDIM, 16);
            cp_async16(sb + B_OFF + st * B_ST + b_loff1, b_src1 + (size_t)ko * NDIM, 16);
        }
        asm volatile("cp.async.commit_group;\n");

        const int buf = s % STAGES;
        const uint32_t abase = sb + A_OFF + buf * A_ST;
        const uint32_t bbase = sb + B_OFF + buf * B_ST;
        #pragma unroll
        for (int ks = 0; ks < 2; ks++) {
            uint32_t afr[2][4];
            #pragma unroll
            for (int mt = 0; mt < 2; mt++) {
                int row = wm * 32 + mt * 16 + (lane & 15);
                ldsm_x4(afr[mt], abase + row * A_ROWB + ks * 32 + ((lane >> 4) << 4));
            }
            uint32_t bfr[4][4];
            #pragma unroll
            for (int pr = 0; pr < 4; pr++) {
                int row = ks * 16 + (lane & 15);
                int col = wn * 64 + pr * 16 + ((lane >> 4) << 3);
                ldsm_x4_trans(bfr[pr], bbase + row * B_ROWB + col * 2);
            }
            #pragma unroll
            for (int mt = 0; mt < 2; mt++)
                #pragma unroll
                for (int nt = 0; nt < 8; nt++) {
                    int pr = nt >> 1;
                    int hb = (nt & 1) * 2;
                    mma_bf16(acc[mt][nt], afr[mt], bfr[pr][hb], bfr[pr][hb + 1]);
                }
        }
    }

    // ---- epilogue ----
    #pragma unroll
    for (int mt = 0; mt < 2; mt++) {
        int gm0 = m0 + wm * 32 + mt * 16 + (lane >> 2);
        int gm1 = gm0 + 8;
        bool ok0 = gm0 < cnt, ok1 = gm1 < cnt;
        int tok0 = ok0 ? toks[gm0] : 0;
        int tok1 = ok1 ? toks[gm1] : 0;
        float tv0 = 0.f, tv1 = 0.f;
        if (EPI == 1) {
            tv0 = ok0 ? g_topval[tok0] : 0.f;
            tv1 = ok1 ? g_topval[tok1] : 0.f;
        }
        #pragma unroll
        for (int nt = 0; nt < 8; nt++) {
            int lc = wn * 64 + nt * 8 + (lane & 3) * 2;
            float bv0 = sbias[lc], bv1 = sbias[lc + 1];
            float* a = acc[mt][nt];
            if (EPI == 0) {
                if (ok0) {
                    __nv_bfloat162 v = __floats2bfloat162_rn(
                        gelu_exact(a[0] + bv0), gelu_exact(a[1] + bv1));
                    *(__nv_bfloat162*)(g_hb + (size_t)tok0 * H_DIM + n0 + lc) = v;
                }
                if (ok1) {
                    __nv_bfloat162 v = __floats2bfloat162_rn(
                        gelu_exact(a[2] + bv0), gelu_exact(a[3] + bv1));
                    *(__nv_bfloat162*)(g_hb + (size_t)tok1 * H_DIM + n0 + lc) = v;
                }
            } else {
                if (ok0) {
                    float2 v = make_float2((a[0] + bv0) * tv0, (a[1] + bv1) * tv0);
                    *(float2*)(g_y + (size_t)tok0 * D_DIM + n0 + lc) = v;
                }
                if (ok1) {
                    float2 v = make_float2((a[2] + bv0) * tv1, (a[3] + bv1) * tv1);
                    *(float2*)(g_y + (size_t)tok1 * D_DIM + n0 + lc) = v;
                }
            }
        }
    }
}

// ---------------- 4: residual + L2-normalize + gamma*sqrt(D) + gelu ----------------
__global__ void finalize_kernel(const float* __restrict__ x,
                                const float* __restrict__ gamma,
                                float* __restrict__ out) {
    const int t   = blockIdx.x;
    const int tid = threadIdx.x;
    const float* xr = x  + (size_t)t * D_DIM;
    const float* er = g_y + (size_t)t * D_DIM;
    float yv[4];
    float ss = 0.f;
    #pragma unroll
    for (int i = 0; i < 4; i++) {
        int d = i * 256 + tid;
        float v = xr[d] + er[d];
        yv[i] = v;
        ss += v * v;
    }
    __shared__ float red[256];
    red[tid] = ss;
    __syncthreads();
    #pragma unroll
    for (int o = 128; o > 0; o >>= 1) {
        if (tid < o) red[tid] += red[tid + o];
        __syncthreads();
    }
    float nrm   = sqrtf(red[0]);
    float scale = 32.0f / fmaxf(nrm, 1e-12f);
    float* orow = out + (size_t)t * D_DIM;
    #pragma unroll
    for (int i = 0; i < 4; i++) {
        int d = i * 256 + tid;
        float v = yv[i] * scale * gamma[d];
        orow[d] = gelu_exact(v);
    }
}

// ---------------- 5: load-balance loss ----------------
__global__ void loss_kernel(float* __restrict__ out, int out_size) {
    __shared__ float red[256];
    __shared__ float imp[E_NUM];
    const int tid = threadIdx.x;
    for (int e = 0; e < E_NUM; e++) {
        float s = 0.f;
        for (int t = tid; t < T_TOKENS; t += 256)
            s += g_probs[t * E_NUM + e];
        red[tid] = s;
        __syncthreads();
        #pragma unroll
        for (int o = 128; o > 0; o >>= 1) {
            if (tid < o) red[tid] += red[tid + o];
            __syncthreads();
        }
        if (tid == 0) imp[e] = red[0];
        __syncthreads();
    }
    if (tid == 0) {
        float sum = 0.f;
        #pragma unroll
        for (int e = 0; e < E_NUM; e++) sum += imp[e];
        float mean = sum / (float)E_NUM;
        float var = 0.f;
        #pragma unroll
        for (int e = 0; e < E_NUM; e++) {
            float dlt = imp[e] - mean;
            var += dlt * dlt;
        }
        var /= (float)(E_NUM - 1);
        float loss = var / (mean * mean + 1e-10f);
        if (out_size > T_TOKENS * D_DIM)
            out[T_TOKENS * D_DIM] = loss;
    }
}

// ---------------- launch (3 streams, two expert-group chains) ----------------
extern "C" void kernel_launch(void* const* d_in, const int* in_sizes, int n_in,
                              void* d_out, int out_size) {
    const float* x     = (const float*)d_in[0];
    const float* gw    = (const float*)d_in[1];
    const float* gb    = (const float*)d_in[2];
    const float* w1    = (const float*)d_in[3];
    const float* b1    = (const float*)d_in[4];
    const float* w2    = (const float*)d_in[5];
    const float* b2    = (const float*)d_in[6];
    const float* gamma = (const float*)d_in[7];
    float* out = (float*)d_out;

    __nv_bfloat16 *xb, *w1b, *w2b, *hb;
    cudaGetSymbolAddress((void**)&xb,  g_xb);
    cudaGetSymbolAddress((void**)&w1b, g_w1b);
    cudaGetSymbolAddress((void**)&w2b, g_w2b);
    cudaGetSymbolAddress((void**)&hb,  g_hb);

    static bool init_done = false;
    static cudaStream_t s1, s2, s3;
    static cudaEvent_t ev_fork, ev_w1, ev_w2, ev_gate, ev_xb, ev_loss, ev_gB;
    if (!init_done) {
        cudaStreamCreateWithFlags(&s1, cudaStreamNonBlocking);
        cudaStreamCreateWithFlags(&s2, cudaStreamNonBlocking);
        cudaStreamCreateWithFlags(&s3, cudaStreamNonBlocking);
        cudaEventCreateWithFlags(&ev_fork, cudaEventDisableTiming);
        cudaEventCreateWithFlags(&ev_w1,   cudaEventDisableTiming);
        cudaEventCreateWithFlags(&ev_w2,   cudaEventDisableTiming);
        cudaEventCreateWithFlags(&ev_gate, cudaEventDisableTiming);
        cudaEventCreateWithFlags(&ev_xb,   cudaEventDisableTiming);
        cudaEventCreateWithFlags(&ev_loss, cudaEventDisableTiming);
        cudaEventCreateWithFlags(&ev_gB,   cudaEventDisableTiming);
        cudaFuncSetAttribute(moe_gemm<D_DIM, H_DIM, 0>,
                             cudaFuncAttributeMaxDynamicSharedMemorySize, SMEM_BYTES);
        cudaFuncSetAttribute(moe_gemm<H_DIM, D_DIM, 1>,
                             cudaFuncAttributeMaxDynamicSharedMemorySize, SMEM_BYTES);
        init_done = true;
    }

    const int nw = E_NUM * D_DIM * H_DIM;

    // fork
    cudaEventRecord(ev_fork, 0);
    cudaStreamWaitEvent(s1, ev_fork, 0);
    cudaStreamWaitEvent(s2, ev_fork, 0);
    cudaStreamWaitEvent(s3, ev_fork, 0);

    // s1: w1 convert ; s2: w2 convert
    convert_kernel<<<(nw / 4 + 255) / 256, 256, 0, s1>>>(w1, w1b, nw);
    cudaEventRecord(ev_w1, s1);
    convert_kernel<<<(nw / 4 + 255) / 256, 256, 0, s2>>>(w2, w2b, nw);
    cudaEventRecord(ev_w2, s2);

    // s3: routing chain + loss (loss concurrent with GEMMs)
    zero_kernel<<<1, 32, 0, s3>>>();
    gate_kernel<<<T_TOKENS / 8, 256, 0, s3>>>(x, gw, gb);
    cudaEventRecord(ev_gate, s3);
    loss_kernel<<<1, 256, 0, s3>>>(out, out_size);
    cudaEventRecord(ev_loss, s3);

    // main: x convert
    {
        int n = T_TOKENS * D_DIM;
        convert_kernel<<<(n / 4 + 255) / 256, 256>>>(x, xb, n);
    }
    cudaEventRecord(ev_xb, 0);

    // chain A (experts 0..3) on main stream
    cudaStreamWaitEvent(0, ev_gate, 0);
    cudaStreamWaitEvent(0, ev_w1, 0);
    moe_gemm<D_DIM, H_DIM, 0>
        <<<dim3(H_DIM / BN, T_TOKENS / BM, 4), 512, SMEM_BYTES>>>(xb, w1b, b1, 0);
    cudaStreamWaitEvent(0, ev_w2, 0);
    moe_gemm<H_DIM, D_DIM, 1>
        <<<dim3(D_DIM / BN, T_TOKENS / BM, 4), 512, SMEM_BYTES>>>(hb, w2b, b2, 0);

    // chain B (experts 4..7) on s1 (w1 convert already in its program order)
    cudaStreamWaitEvent(s1, ev_gate, 0);
    cudaStreamWaitEvent(s1, ev_xb, 0);
    moe_gemm<D_DIM, H_DIM, 0>
        <<<dim3(H_DIM / BN, T_TOKENS / BM, 4), 512, SMEM_BYTES, s1>>>(xb, w1b, b1, 4);
    cudaStreamWaitEvent(s1, ev_w2, 0);
    moe_gemm<H_DIM, D_DIM, 1>
        <<<dim3(D_DIM / BN, T_TOKENS / BM, 4), 512, SMEM_BYTES, s1>>>(hb, w2b, b2, 4);
    cudaEventRecord(ev_gB, s1);

    // join both chains -> finalize
    cudaStreamWaitEvent(0, ev_gB, 0);
    finalize_kernel<<<T_TOKENS, 256>>>(x, gamma, out);
    cudaStreamWaitEvent(0, ev_loss, 0);
}